// round 8
// baseline (speedup 1.0000x reference)
#include <cuda_runtime.h>
#include <math.h>
#include <stdint.h>

#define I_DIM 384
#define J_DIM 384
#define C_DIM 128
#define H_DIM 4
#define ROWS (I_DIM * J_DIM)          // 147456
#define LN_EPS 1e-5f
#define LOG2E 1.4426950408889634f

// ---------------- scratch -----------------------------------------------
__device__ float g_xn[ROWS * C_DIM];
__device__ float g_tri[H_DIM * ROWS];   // [h][q*384+k], pre-scaled by LOG2E
__device__ float g_q[ROWS * C_DIM];     // pre-scaled by (1/sqrt(32))*LOG2E
__device__ float g_k[ROWS * C_DIM];
__device__ float g_v[ROWS * C_DIM];
__device__ float g_g[ROWS * C_DIM];
__device__ float g_o[ROWS * C_DIM];

// ---------------- helpers -----------------------------------------------
__device__ __forceinline__ uint32_t f2tf(float x) {
    uint32_t r; asm("cvt.rna.tf32.f32 %0, %1;" : "=r"(r) : "f"(x)); return r;
}
__device__ __forceinline__ float tf2f(float x) {
    return __uint_as_float(f2tf(x));
}
__device__ __forceinline__ float ex2(float x) {
    float r; asm("ex2.approx.ftz.f32 %0, %1;" : "=f"(r) : "f"(x)); return r;
}
__device__ __forceinline__ void mma8(float* c, const uint32_t* a,
                                     uint32_t b0, uint32_t b1) {
    asm volatile(
        "mma.sync.aligned.m16n8k8.row.col.f32.tf32.tf32.f32 "
        "{%0,%1,%2,%3},{%4,%5,%6,%7},{%8,%9},{%0,%1,%2,%3};"
        : "+f"(c[0]), "+f"(c[1]), "+f"(c[2]), "+f"(c[3])
        : "r"(a[0]), "r"(a[1]), "r"(a[2]), "r"(a[3]), "r"(b0), "r"(b1));
}
#define BITS(x) __float_as_uint(x)

// ---------------- Kernel 1: LN + tri (warp per row) ----------------------
__global__ __launch_bounds__(256) void ln_tri_kernel(
    const float* __restrict__ x, const float* __restrict__ ln_g,
    const float* __restrict__ ln_b, const float* __restrict__ w_tri)
{
    int row  = blockIdx.x * 8 + (threadIdx.x >> 5);
    int lane = threadIdx.x & 31;

    float4 v = ((const float4*)x)[(size_t)row * 32 + lane];
    float s = v.x + v.y + v.z + v.w;
    #pragma unroll
    for (int o = 16; o; o >>= 1) s += __shfl_xor_sync(~0u, s, o);
    float mean = s * (1.0f / 128.0f);

    float4 d = make_float4(v.x - mean, v.y - mean, v.z - mean, v.w - mean);
    float s2 = d.x*d.x + d.y*d.y + d.z*d.z + d.w*d.w;
    #pragma unroll
    for (int o = 16; o; o >>= 1) s2 += __shfl_xor_sync(~0u, s2, o);
    float rstd = rsqrtf(s2 * (1.0f / 128.0f) + LN_EPS);

    float4 gg = ((const float4*)ln_g)[lane];
    float4 bb = ((const float4*)ln_b)[lane];
    float4 xn;
    xn.x = d.x * rstd * gg.x + bb.x;
    xn.y = d.y * rstd * gg.y + bb.y;
    xn.z = d.z * rstd * gg.z + bb.z;
    xn.w = d.w * rstd * gg.w + bb.w;
    ((float4*)g_xn)[(size_t)row * 32 + lane] = xn;

    const float4* wt = (const float4*)w_tri;
    float4 w0 = wt[lane*4+0], w1 = wt[lane*4+1], w2 = wt[lane*4+2], w3 = wt[lane*4+3];
    float p0 = xn.x*w0.x + xn.y*w1.x + xn.z*w2.x + xn.w*w3.x;
    float p1 = xn.x*w0.y + xn.y*w1.y + xn.z*w2.y + xn.w*w3.y;
    float p2 = xn.x*w0.z + xn.y*w1.z + xn.z*w2.z + xn.w*w3.z;
    float p3 = xn.x*w0.w + xn.y*w1.w + xn.z*w2.w + xn.w*w3.w;
    #pragma unroll
    for (int o = 16; o; o >>= 1) {
        p0 += __shfl_xor_sync(~0u, p0, o);
        p1 += __shfl_xor_sync(~0u, p1, o);
        p2 += __shfl_xor_sync(~0u, p2, o);
        p3 += __shfl_xor_sync(~0u, p3, o);
    }
    if (lane < 4) {
        float pv = (lane == 0) ? p0 : (lane == 1) ? p1 : (lane == 2) ? p2 : p3;
        g_tri[(size_t)lane * ROWS + row] = pv * LOG2E;
    }
}

// ---------------- GEMM: 64x128 tile, 8 warps (2x4), warp tile 32x32 ------
#define SA 132
#define SB 136

#define MMA_MAINLOOP(ACC)                                              \
    _Pragma("unroll")                                                  \
    for (int ks = 0; ks < 16; ks++) {                                  \
        int k0 = ks * 8;                                               \
        uint32_t a[2][4];                                              \
        _Pragma("unroll")                                              \
        for (int mt = 0; mt < 2; mt++) {                               \
            int rb = warpM + mt * 16 + r8;                             \
            a[mt][0] = BITS(As[rb * SA + k0 + q4]);                    \
            a[mt][1] = BITS(As[(rb + 8) * SA + k0 + q4]);              \
            a[mt][2] = BITS(As[rb * SA + k0 + q4 + 4]);                \
            a[mt][3] = BITS(As[(rb + 8) * SA + k0 + q4 + 4]);          \
        }                                                              \
        _Pragma("unroll")                                              \
        for (int nt = 0; nt < 4; nt++) {                               \
            int nb = warpN + nt * 8 + r8;                              \
            uint32_t b0 = BITS(Bs[(k0 + q4) * SB + nb]);               \
            uint32_t b1 = BITS(Bs[(k0 + q4 + 4) * SB + nb]);           \
            mma8(ACC[0][nt], a[0], b0, b1);                            \
            mma8(ACC[1][nt], a[1], b0, b1);                            \
        }                                                              \
    }

// ---------------- Kernel 2: fused q/k/v/g projection ---------------------
__global__ __launch_bounds__(256, 2) void proj_kernel(
    const float* __restrict__ wq, const float* __restrict__ wk,
    const float* __restrict__ wv, const float* __restrict__ wg,
    const float* __restrict__ bg)
{
    extern __shared__ float sh[];
    float* As = sh;                 // [64][SA]
    float* Bs = sh + 64 * SA;       // [128][SB]

    int m0 = blockIdx.x * 64;
    int tid = threadIdx.x, wid = tid >> 5, lane = tid & 31;
    int warpM = (wid >> 2) * 32, warpN = (wid & 3) * 32;
    int q4 = lane & 3, r8 = lane >> 2;

    const float4* A4 = (const float4*)g_xn + (size_t)m0 * 32;
    #pragma unroll
    for (int it = 0; it < 8; it++) {
        int idx = tid + it * 256;
        int rr = idx >> 5, c4 = idx & 31;
        float4 v = A4[rr * 32 + c4];
        float* dst = As + rr * SA + c4 * 4;
        dst[0] = tf2f(v.x); dst[1] = tf2f(v.y); dst[2] = tf2f(v.z); dst[3] = tf2f(v.w);
    }

    #pragma unroll 1
    for (int y = 0; y < 4; y++) {
        const float* W = (y == 0) ? wq : (y == 1) ? wk : (y == 2) ? wv : wg;
        float*       O = (y == 0) ? g_q : (y == 1) ? g_k : (y == 2) ? g_v : g_g;

        __syncthreads();
        const float4* W4 = (const float4*)W;
        #pragma unroll
        for (int it = 0; it < 16; it++) {
            int idx = tid + it * 256;
            int kk = idx >> 5, c4 = idx & 31;
            float4 v = W4[idx];
            float* dst = Bs + kk * SB + c4 * 4;
            dst[0] = tf2f(v.x); dst[1] = tf2f(v.y); dst[2] = tf2f(v.z); dst[3] = tf2f(v.w);
        }
        __syncthreads();

        float acc[2][4][4];
        #pragma unroll
        for (int mt = 0; mt < 2; mt++)
            #pragma unroll
            for (int nt = 0; nt < 4; nt++)
                #pragma unroll
                for (int u = 0; u < 4; u++) acc[mt][nt][u] = 0.0f;

        MMA_MAINLOOP(acc)

        const float qscale = 0.17677669529663687f * LOG2E;
        #pragma unroll
        for (int mt = 0; mt < 2; mt++) {
            int row0 = m0 + warpM + mt * 16 + r8;
            #pragma unroll
            for (int nt = 0; nt < 4; nt++) {
                int col = warpN + nt * 8 + 2 * q4;
                float v0 = acc[mt][nt][0], v1 = acc[mt][nt][1];
                float v2 = acc[mt][nt][2], v3 = acc[mt][nt][3];
                if (y == 0) { v0 *= qscale; v1 *= qscale; v2 *= qscale; v3 *= qscale; }
                if (y == 3) {
                    float b0v = bg[col], b1v = bg[col + 1];
                    v0 = 1.0f / (1.0f + __expf(-(v0 + b0v)));
                    v1 = 1.0f / (1.0f + __expf(-(v1 + b1v)));
                    v2 = 1.0f / (1.0f + __expf(-(v2 + b0v)));
                    v3 = 1.0f / (1.0f + __expf(-(v3 + b1v)));
                }
                *(float2*)&O[(size_t)row0 * 128 + col]       = make_float2(v0, v1);
                *(float2*)&O[(size_t)(row0 + 8) * 128 + col] = make_float2(v2, v3);
            }
        }
    }
}

// ---------------- Kernel 3: tf32 MMA flash attention (fixed-shift) -------
// block = (i,h), 768 threads = 24 warps, each warp owns 16 query rows.
// Softmax uses a fixed shift (clamped exp2) instead of online max: logits
// here are O(1) for unmasked keys and -1.4e9 (exp2 -> 0) for masked ones,
// so the running max machinery is pure overhead. l reduced once at the end.
#define KSTR 36
#define VSTR 40

__global__ __launch_bounds__(768) void attn_kernel(const float* __restrict__ mask)
{
    extern __shared__ float sh[];
    float* Ksh = sh;                          // [384][KSTR]
    float* Vsh = sh + 384 * KSTR;             // [384][VSTR]
    float* mb  = sh + 384 * KSTR + 384 * VSTR;// [384]

    int i = blockIdx.x, h = blockIdx.y;
    int tid = threadIdx.x, wid = tid >> 5, lane = tid & 31;
    int q4 = lane & 3, r8 = lane >> 2;

    const float4* K4 = (const float4*)g_k + (size_t)i * J_DIM * 32 + h * 8;
    const float4* V4 = (const float4*)g_v + (size_t)i * J_DIM * 32 + h * 8;
    #pragma unroll
    for (int it = 0; it < 4; it++) {
        int idx = tid + it * 768;
        int j = idx >> 3, d4 = idx & 7;
        float4 kv = K4[(size_t)j * 32 + d4];
        float4 vv = V4[(size_t)j * 32 + d4];
        float4 kt = make_float4(tf2f(kv.x), tf2f(kv.y), tf2f(kv.z), tf2f(kv.w));
        float4 vt = make_float4(tf2f(vv.x), tf2f(vv.y), tf2f(vv.z), tf2f(vv.w));
        *(float4*)(Ksh + j * KSTR + d4 * 4) = kt;
        *(float4*)(Vsh + j * VSTR + d4 * 4) = vt;
    }
    if (tid < 384)
        mb[tid] = (LOG2E * 1.0e9f) * (mask[(size_t)i * J_DIM + tid] - 1.0f);
    __syncthreads();

    int qbase = wid * 16;
    uint32_t qa[4][4];
    {
        const float* Qp = g_q + ((size_t)i * J_DIM + qbase) * 128 + h * 32;
        #pragma unroll
        for (int ksp = 0; ksp < 4; ksp++) {
            const float* Qk = Qp + ksp * 8;
            qa[ksp][0] = f2tf(Qk[r8 * 128 + q4]);
            qa[ksp][1] = f2tf(Qk[(r8 + 8) * 128 + q4]);
            qa[ksp][2] = f2tf(Qk[r8 * 128 + q4 + 4]);
            qa[ksp][3] = f2tf(Qk[(r8 + 8) * 128 + q4 + 4]);
        }
    }

    float oacc[4][4];
    #pragma unroll
    for (int dn = 0; dn < 4; dn++)
        #pragma unroll
        for (int u = 0; u < 4; u++) oacc[dn][u] = 0.0f;
    float lrow0 = 0.0f, lrow1 = 0.0f;      // per-thread partial sums

    const float* triW = g_tri + (size_t)h * ROWS;
    int srcA = (lane & ~3) | (q4 >> 1);
    int srcB = srcA + 2;
    bool odd = (q4 & 1) != 0;

    #pragma unroll 1
    for (int kb = 0; kb < 12; kb++) {
        int kbase = kb * 32;

        // ---- S = Q K^T (16 rows x 32 keys) ----
        float sacc[4][4];
        #pragma unroll
        for (int nt = 0; nt < 4; nt++)
            #pragma unroll
            for (int u = 0; u < 4; u++) sacc[nt][u] = 0.0f;

        #pragma unroll
        for (int nt = 0; nt < 4; nt++) {
            const float* Kp = Ksh + (kbase + nt * 8 + r8) * KSTR;
            #pragma unroll
            for (int ksp = 0; ksp < 4; ksp++) {
                uint32_t b0 = BITS(Kp[ksp * 8 + q4]);
                uint32_t b1 = BITS(Kp[ksp * 8 + q4 + 4]);
                mma8(sacc[nt], qa[ksp], b0, b1);
            }
        }

        // ---- bias + fixed-shift exp2 (no online max) ----
        {
            int qrow = qbase + r8;
            const float* t0p = triW + (size_t)qrow * J_DIM + kbase + 2 * q4;
            const float* t1p = t0p + 8 * J_DIM;
            #pragma unroll
            for (int nt = 0; nt < 4; nt++) {
                float2 tA = *(const float2*)(t0p + nt * 8);
                float2 tB = *(const float2*)(t1p + nt * 8);
                float2 mv = *(const float2*)(mb + kbase + nt * 8 + 2 * q4);
                float* s = sacc[nt];
                s[0] = ex2(fminf(s[0] + tA.x + mv.x, 30.0f));
                s[1] = ex2(fminf(s[1] + tA.y + mv.y, 30.0f));
                s[2] = ex2(fminf(s[2] + tB.x + mv.x, 30.0f));
                s[3] = ex2(fminf(s[3] + tB.y + mv.y, 30.0f));
                lrow0 += s[0] + s[1];
                lrow1 += s[2] + s[3];
            }
        }

        // ---- O += P V ----
        #pragma unroll
        for (int kc = 0; kc < 4; kc++) {
            uint32_t pa[4];
            {
                uint32_t t0 = f2tf(sacc[kc][0]);
                uint32_t t1 = f2tf(sacc[kc][1]);
                uint32_t t2 = f2tf(sacc[kc][2]);
                uint32_t t3 = f2tf(sacc[kc][3]);
                uint32_t e0 = __shfl_sync(~0u, t0, srcA), o0 = __shfl_sync(~0u, t1, srcA);
                uint32_t e1 = __shfl_sync(~0u, t2, srcA), o1 = __shfl_sync(~0u, t3, srcA);
                uint32_t e2 = __shfl_sync(~0u, t0, srcB), o2 = __shfl_sync(~0u, t1, srcB);
                uint32_t e3 = __shfl_sync(~0u, t2, srcB), o3 = __shfl_sync(~0u, t3, srcB);
                pa[0] = odd ? o0 : e0;
                pa[1] = odd ? o1 : e1;
                pa[2] = odd ? o2 : e2;
                pa[3] = odd ? o3 : e3;
            }
            int kk = kbase + kc * 8 + q4;
            #pragma unroll
            for (int dn = 0; dn < 4; dn++) {
                int dd = dn * 8 + r8;
                uint32_t b0 = BITS(Vsh[kk * VSTR + dd]);
                uint32_t b1 = BITS(Vsh[(kk + 4) * VSTR + dd]);
                mma8(oacc[dn], pa, b0, b1);
            }
        }
    }

    // ---- final l reduction across the 4 threads of each row ----
    lrow0 += __shfl_xor_sync(~0u, lrow0, 1);
    lrow0 += __shfl_xor_sync(~0u, lrow0, 2);
    lrow1 += __shfl_xor_sync(~0u, lrow1, 1);
    lrow1 += __shfl_xor_sync(~0u, lrow1, 2);

    // ---- finalize: 1/l, gate, store ----
    {
        float inv0 = 1.0f / fmaxf(lrow0, 1e-30f);
        float inv1 = 1.0f / fmaxf(lrow1, 1e-30f);
        size_t row0 = ((size_t)i * J_DIM + qbase + r8) * 128 + h * 32;
        size_t row1 = row0 + (size_t)8 * 128;
        #pragma unroll
        for (int dn = 0; dn < 4; dn++) {
            int c = dn * 8 + 2 * q4;
            float2 gv0 = *(const float2*)(g_g + row0 + c);
            float2 gv1 = *(const float2*)(g_g + row1 + c);
            *(float2*)(g_o + row0 + c) =
                make_float2(oacc[dn][0] * inv0 * gv0.x,
                            oacc[dn][1] * inv0 * gv0.y);
            *(float2*)(g_o + row1 + c) =
                make_float2(oacc[dn][2] * inv1 * gv1.x,
                            oacc[dn][3] * inv1 * gv1.y);
        }
    }
}

// ---------------- Kernel 4: output projection (tf32 MMA) ------------------
__global__ __launch_bounds__(256, 2) void out_kernel(
    const float* __restrict__ wo, const float* __restrict__ bo,
    float* __restrict__ out)
{
    extern __shared__ float sh[];
    float* As = sh;                 // [64][SA]
    float* Bs = sh + 64 * SA;       // [128][SB]

    int m0 = blockIdx.x * 64;
    int tid = threadIdx.x, wid = tid >> 5, lane = tid & 31;
    int warpM = (wid >> 2) * 32, warpN = (wid & 3) * 32;
    int q4 = lane & 3, r8 = lane >> 2;

    const float4* A4 = (const float4*)g_o + (size_t)m0 * 32;
    #pragma unroll
    for (int it = 0; it < 8; it++) {
        int idx = tid + it * 256;
        int rr = idx >> 5, c4 = idx & 31;
        float4 v = A4[rr * 32 + c4];
        float* dst = As + rr * SA + c4 * 4;
        dst[0] = tf2f(v.x); dst[1] = tf2f(v.y); dst[2] = tf2f(v.z); dst[3] = tf2f(v.w);
    }
    const float4* W4 = (const float4*)wo;
    #pragma unroll
    for (int it = 0; it < 16; it++) {
        int idx = tid + it * 256;
        int kk = idx >> 5, c4 = idx & 31;
        float4 v = W4[idx];
        float* dst = Bs + kk * SB + c4 * 4;
        dst[0] = tf2f(v.x); dst[1] = tf2f(v.y); dst[2] = tf2f(v.z); dst[3] = tf2f(v.w);
    }
    __syncthreads();

    float acc[2][4][4];
    #pragma unroll
    for (int mt = 0; mt < 2; mt++)
        #pragma unroll
        for (int nt = 0; nt < 4; nt++)
            #pragma unroll
            for (int u = 0; u < 4; u++) acc[mt][nt][u] = 0.0f;

    MMA_MAINLOOP(acc)

    #pragma unroll
    for (int mt = 0; mt < 2; mt++) {
        int row0 = m0 + warpM + mt * 16 + r8;
        #pragma unroll
        for (int nt = 0; nt < 4; nt++) {
            int col = warpN + nt * 8 + 2 * q4;
            float b0v = bo[col], b1v = bo[col + 1];
            *(float2*)&out[(size_t)row0 * 128 + col] =
                make_float2(acc[mt][nt][0] + b0v, acc[mt][nt][1] + b1v);
            *(float2*)&out[(size_t)(row0 + 8) * 128 + col] =
                make_float2(acc[mt][nt][2] + b0v, acc[mt][nt][3] + b1v);
        }
    }
}

// ---------------- launch --------------------------------------------------
extern "C" void kernel_launch(void* const* d_in, const int* in_sizes, int n_in,
                              void* d_out, int out_size)
{
    const float* x     = (const float*)d_in[0];
    const float* mask  = (const float*)d_in[1];
    const float* ln_g  = (const float*)d_in[2];
    const float* ln_b  = (const float*)d_in[3];
    const float* w_tri = (const float*)d_in[4];
    const float* wq    = (const float*)d_in[5];
    const float* wk    = (const float*)d_in[6];
    const float* wv    = (const float*)d_in[7];
    const float* wg    = (const float*)d_in[8];
    const float* bg    = (const float*)d_in[9];
    const float* wo    = (const float*)d_in[10];
    const float* bo    = (const float*)d_in[11];
    float* out = (float*)d_out;

    const int SMEM_GEMM = (64 * SA + 128 * SB) * (int)sizeof(float);           // 103424
    const int SMEM_ATTN = (384 * KSTR + 384 * VSTR + 384) * (int)sizeof(float); // 118272
    cudaFuncSetAttribute(proj_kernel,
                         cudaFuncAttributeMaxDynamicSharedMemorySize, SMEM_GEMM);
    cudaFuncSetAttribute(out_kernel,
                         cudaFuncAttributeMaxDynamicSharedMemorySize, SMEM_GEMM);
    cudaFuncSetAttribute(attn_kernel,
                         cudaFuncAttributeMaxDynamicSharedMemorySize, SMEM_ATTN);

    ln_tri_kernel<<<ROWS / 8, 256>>>(x, ln_g, ln_b, w_tri);
    proj_kernel<<<ROWS / 64, 256, SMEM_GEMM>>>(wq, wk, wv, wg, bg);
    attn_kernel<<<dim3(I_DIM, H_DIM), 768, SMEM_ATTN>>>(mask);
    out_kernel<<<ROWS / 64, 256, SMEM_GEMM>>>(wo, bo, out);
}

// round 9
// speedup vs baseline: 1.5043x; 1.5043x over previous
#include <cuda_runtime.h>
#include <math.h>
#include <stdint.h>

#define I_DIM 384
#define J_DIM 384
#define C_DIM 128
#define H_DIM 4
#define ROWS (I_DIM * J_DIM)          // 147456
#define LN_EPS 1e-5f
#define LOG2E 1.4426950408889634f

// ---------------- scratch -----------------------------------------------
__device__ float g_tri[H_DIM * ROWS];   // [h][q*384+k], pre-scaled by LOG2E
__device__ float g_q[ROWS * C_DIM];     // pre-scaled by (1/sqrt(32))*LOG2E
__device__ float g_k[ROWS * C_DIM];
__device__ float g_v[ROWS * C_DIM];
__device__ float g_g[ROWS * C_DIM];
__device__ float g_o[ROWS * C_DIM];

// ---------------- helpers -----------------------------------------------
__device__ __forceinline__ uint32_t f2tf(float x) {
    uint32_t r; asm("cvt.rna.tf32.f32 %0, %1;" : "=r"(r) : "f"(x)); return r;
}
__device__ __forceinline__ float tf2f(float x) {
    return __uint_as_float(f2tf(x));
}
__device__ __forceinline__ float ex2(float x) {
    float r; asm("ex2.approx.ftz.f32 %0, %1;" : "=f"(r) : "f"(x)); return r;
}
__device__ __forceinline__ void mma8(float* c, const uint32_t* a,
                                     uint32_t b0, uint32_t b1) {
    asm volatile(
        "mma.sync.aligned.m16n8k8.row.col.f32.tf32.tf32.f32 "
        "{%0,%1,%2,%3},{%4,%5,%6,%7},{%8,%9},{%0,%1,%2,%3};"
        : "+f"(c[0]), "+f"(c[1]), "+f"(c[2]), "+f"(c[3])
        : "r"(a[0]), "r"(a[1]), "r"(a[2]), "r"(a[3]), "r"(b0), "r"(b1));
}
#define BITS(x) __float_as_uint(x)

// ---------------- GEMM: 64x128 tile, 8 warps (2x4), warp tile 32x32 ------
#define SA 132
#define SB 136

#define MMA_MAINLOOP(ACC)                                              \
    _Pragma("unroll")                                                  \
    for (int ks = 0; ks < 16; ks++) {                                  \
        int k0 = ks * 8;                                               \
        uint32_t a[2][4];                                              \
        _Pragma("unroll")                                              \
        for (int mt = 0; mt < 2; mt++) {                               \
            int rb = warpM + mt * 16 + r8;                             \
            a[mt][0] = BITS(As[rb * SA + k0 + q4]);                    \
            a[mt][1] = BITS(As[(rb + 8) * SA + k0 + q4]);              \
            a[mt][2] = BITS(As[rb * SA + k0 + q4 + 4]);                \
            a[mt][3] = BITS(As[(rb + 8) * SA + k0 + q4 + 4]);          \
        }                                                              \
        _Pragma("unroll")                                              \
        for (int nt = 0; nt < 4; nt++) {                               \
            int nb = warpN + nt * 8 + r8;                              \
            uint32_t b0 = BITS(Bs[(k0 + q4) * SB + nb]);               \
            uint32_t b1 = BITS(Bs[(k0 + q4 + 4) * SB + nb]);           \
            mma8(ACC[0][nt], a[0], b0, b1);                            \
            mma8(ACC[1][nt], a[1], b0, b1);                            \
        }                                                              \
    }

// ---------------- Kernel 1: fused LN + tri + q/k/v/g projection ----------
// Each block owns 64 rows: stages raw x coalesced, LayerNorms in smem
// (4 threads/row x 32 channels, 4-lane shuffle reductions), emits tri bias,
// then runs the 4 weight GEMMs on the normalized tf32 tile.
__global__ __launch_bounds__(256, 2) void proj_kernel(
    const float* __restrict__ x,
    const float* __restrict__ ln_g, const float* __restrict__ ln_b,
    const float* __restrict__ w_tri,
    const float* __restrict__ wq, const float* __restrict__ wk,
    const float* __restrict__ wv, const float* __restrict__ wg,
    const float* __restrict__ bg)
{
    extern __shared__ float sh[];
    float* As = sh;                 // [64][SA]
    float* Bs = sh + 64 * SA;       // [128][SB]

    int m0 = blockIdx.x * 64;
    int tid = threadIdx.x, wid = tid >> 5, lane = tid & 31;
    int warpM = (wid >> 2) * 32, warpN = (wid & 3) * 32;
    int q4 = lane & 3, r8 = lane >> 2;

    // ---- stage raw x (coalesced) ----
    const float4* X4 = (const float4*)x + (size_t)m0 * 32;
    #pragma unroll
    for (int it = 0; it < 8; it++) {
        int idx = tid + it * 256;           // 0..2047 float4s
        int rr = idx >> 5, c4 = idx & 31;
        *(float4*)(As + rr * SA + c4 * 4) = X4[idx];
    }
    __syncthreads();

    // ---- LayerNorm + tri: thread (row=tid>>2, quarter=tid&3) ----
    {
        int row = tid >> 2, qq = tid & 3;
        float* rp = As + row * SA + qq * 32;
        float vals[32];
        float sum = 0.0f, ss = 0.0f;
        #pragma unroll
        for (int j = 0; j < 32; j++) {
            float v = rp[j];
            vals[j] = v; sum += v; ss += v * v;
        }
        sum += __shfl_xor_sync(~0u, sum, 1);
        sum += __shfl_xor_sync(~0u, sum, 2);
        ss  += __shfl_xor_sync(~0u, ss, 1);
        ss  += __shfl_xor_sync(~0u, ss, 2);
        float mean = sum * (1.0f / 128.0f);
        float var  = ss * (1.0f / 128.0f) - mean * mean;
        float rstd = rsqrtf(var + LN_EPS);

        const float4* G4 = (const float4*)ln_g + qq * 8;
        const float4* B4 = (const float4*)ln_b + qq * 8;
        const float4* W4 = (const float4*)w_tri + qq * 32;  // w_tri[c][0..3]
        float p0 = 0.0f, p1 = 0.0f, p2 = 0.0f, p3 = 0.0f;
        #pragma unroll
        for (int j4 = 0; j4 < 8; j4++) {
            float4 gg = G4[j4], bb = B4[j4];
            float xn0 = (vals[4*j4+0] - mean) * rstd * gg.x + bb.x;
            float xn1 = (vals[4*j4+1] - mean) * rstd * gg.y + bb.y;
            float xn2 = (vals[4*j4+2] - mean) * rstd * gg.z + bb.z;
            float xn3 = (vals[4*j4+3] - mean) * rstd * gg.w + bb.w;
            rp[4*j4+0] = tf2f(xn0); rp[4*j4+1] = tf2f(xn1);
            rp[4*j4+2] = tf2f(xn2); rp[4*j4+3] = tf2f(xn3);
            float4 w0 = W4[4*j4+0], w1 = W4[4*j4+1];
            float4 w2 = W4[4*j4+2], w3 = W4[4*j4+3];
            p0 += xn0*w0.x + xn1*w1.x + xn2*w2.x + xn3*w3.x;
            p1 += xn0*w0.y + xn1*w1.y + xn2*w2.y + xn3*w3.y;
            p2 += xn0*w0.z + xn1*w1.z + xn2*w2.z + xn3*w3.z;
            p3 += xn0*w0.w + xn1*w1.w + xn2*w2.w + xn3*w3.w;
        }
        #pragma unroll
        for (int o = 1; o <= 2; o <<= 1) {
            p0 += __shfl_xor_sync(~0u, p0, o);
            p1 += __shfl_xor_sync(~0u, p1, o);
            p2 += __shfl_xor_sync(~0u, p2, o);
            p3 += __shfl_xor_sync(~0u, p3, o);
        }
        float pv = (qq == 0) ? p0 : (qq == 1) ? p1 : (qq == 2) ? p2 : p3;
        g_tri[(size_t)qq * ROWS + m0 + row] = pv * LOG2E;
    }

    // ---- 4 weight GEMMs on the normalized tile ----
    #pragma unroll 1
    for (int y = 0; y < 4; y++) {
        const float* W = (y == 0) ? wq : (y == 1) ? wk : (y == 2) ? wv : wg;
        float*       O = (y == 0) ? g_q : (y == 1) ? g_k : (y == 2) ? g_v : g_g;

        __syncthreads();          // LN writes (y=0) / prior readers done
        const float4* W4 = (const float4*)W;
        #pragma unroll
        for (int it = 0; it < 16; it++) {
            int idx = tid + it * 256;
            int kk = idx >> 5, c4 = idx & 31;
            float4 v = W4[idx];
            float* dst = Bs + kk * SB + c4 * 4;
            dst[0] = tf2f(v.x); dst[1] = tf2f(v.y); dst[2] = tf2f(v.z); dst[3] = tf2f(v.w);
        }
        __syncthreads();

        float acc[2][4][4];
        #pragma unroll
        for (int mt = 0; mt < 2; mt++)
            #pragma unroll
            for (int nt = 0; nt < 4; nt++)
                #pragma unroll
                for (int u = 0; u < 4; u++) acc[mt][nt][u] = 0.0f;

        MMA_MAINLOOP(acc)

        const float qscale = 0.17677669529663687f * LOG2E;
        #pragma unroll
        for (int mt = 0; mt < 2; mt++) {
            int row0 = m0 + warpM + mt * 16 + r8;
            #pragma unroll
            for (int nt = 0; nt < 4; nt++) {
                int col = warpN + nt * 8 + 2 * q4;
                float v0 = acc[mt][nt][0], v1 = acc[mt][nt][1];
                float v2 = acc[mt][nt][2], v3 = acc[mt][nt][3];
                if (y == 0) { v0 *= qscale; v1 *= qscale; v2 *= qscale; v3 *= qscale; }
                if (y == 3) {
                    float b0v = bg[col], b1v = bg[col + 1];
                    v0 = 1.0f / (1.0f + __expf(-(v0 + b0v)));
                    v1 = 1.0f / (1.0f + __expf(-(v1 + b1v)));
                    v2 = 1.0f / (1.0f + __expf(-(v2 + b0v)));
                    v3 = 1.0f / (1.0f + __expf(-(v3 + b1v)));
                }
                *(float2*)&O[(size_t)row0 * 128 + col]       = make_float2(v0, v1);
                *(float2*)&O[(size_t)(row0 + 8) * 128 + col] = make_float2(v2, v3);
            }
        }
    }
}

// ---------------- Kernel 2: tf32 MMA flash attention (fixed-shift) -------
#define KSTR 36
#define VSTR 40

__global__ __launch_bounds__(768) void attn_kernel(const float* __restrict__ mask)
{
    extern __shared__ float sh[];
    float* Ksh = sh;                          // [384][KSTR]
    float* Vsh = sh + 384 * KSTR;             // [384][VSTR]
    float* mb  = sh + 384 * KSTR + 384 * VSTR;// [384]

    int i = blockIdx.x, h = blockIdx.y;
    int tid = threadIdx.x, wid = tid >> 5, lane = tid & 31;
    int q4 = lane & 3, r8 = lane >> 2;

    const float4* K4 = (const float4*)g_k + (size_t)i * J_DIM * 32 + h * 8;
    const float4* V4 = (const float4*)g_v + (size_t)i * J_DIM * 32 + h * 8;
    #pragma unroll
    for (int it = 0; it < 4; it++) {
        int idx = tid + it * 768;
        int j = idx >> 3, d4 = idx & 7;
        float4 kv = K4[(size_t)j * 32 + d4];
        float4 vv = V4[(size_t)j * 32 + d4];
        float4 kt = make_float4(tf2f(kv.x), tf2f(kv.y), tf2f(kv.z), tf2f(kv.w));
        float4 vt = make_float4(tf2f(vv.x), tf2f(vv.y), tf2f(vv.z), tf2f(vv.w));
        *(float4*)(Ksh + j * KSTR + d4 * 4) = kt;
        *(float4*)(Vsh + j * VSTR + d4 * 4) = vt;
    }
    if (tid < 384)
        mb[tid] = (LOG2E * 1.0e9f) * (mask[(size_t)i * J_DIM + tid] - 1.0f);
    __syncthreads();

    int qbase = wid * 16;
    uint32_t qa[4][4];
    {
        const float* Qp = g_q + ((size_t)i * J_DIM + qbase) * 128 + h * 32;
        #pragma unroll
        for (int ksp = 0; ksp < 4; ksp++) {
            const float* Qk = Qp + ksp * 8;
            qa[ksp][0] = f2tf(Qk[r8 * 128 + q4]);
            qa[ksp][1] = f2tf(Qk[(r8 + 8) * 128 + q4]);
            qa[ksp][2] = f2tf(Qk[r8 * 128 + q4 + 4]);
            qa[ksp][3] = f2tf(Qk[(r8 + 8) * 128 + q4 + 4]);
        }
    }

    float oacc[4][4];
    #pragma unroll
    for (int dn = 0; dn < 4; dn++)
        #pragma unroll
        for (int u = 0; u < 4; u++) oacc[dn][u] = 0.0f;
    float lrow0 = 0.0f, lrow1 = 0.0f;

    const float* triW = g_tri + (size_t)h * ROWS;
    int srcA = (lane & ~3) | (q4 >> 1);
    int srcB = srcA + 2;
    bool odd = (q4 & 1) != 0;

    #pragma unroll 1
    for (int kb = 0; kb < 12; kb++) {
        int kbase = kb * 32;

        float sacc[4][4];
        #pragma unroll
        for (int nt = 0; nt < 4; nt++)
            #pragma unroll
            for (int u = 0; u < 4; u++) sacc[nt][u] = 0.0f;

        #pragma unroll
        for (int nt = 0; nt < 4; nt++) {
            const float* Kp = Ksh + (kbase + nt * 8 + r8) * KSTR;
            #pragma unroll
            for (int ksp = 0; ksp < 4; ksp++) {
                uint32_t b0 = BITS(Kp[ksp * 8 + q4]);
                uint32_t b1 = BITS(Kp[ksp * 8 + q4 + 4]);
                mma8(sacc[nt], qa[ksp], b0, b1);
            }
        }

        {
            int qrow = qbase + r8;
            const float* t0p = triW + (size_t)qrow * J_DIM + kbase + 2 * q4;
            const float* t1p = t0p + 8 * J_DIM;
            #pragma unroll
            for (int nt = 0; nt < 4; nt++) {
                float2 tA = *(const float2*)(t0p + nt * 8);
                float2 tB = *(const float2*)(t1p + nt * 8);
                float2 mv = *(const float2*)(mb + kbase + nt * 8 + 2 * q4);
                float* s = sacc[nt];
                s[0] = ex2(fminf(s[0] + tA.x + mv.x, 30.0f));
                s[1] = ex2(fminf(s[1] + tA.y + mv.y, 30.0f));
                s[2] = ex2(fminf(s[2] + tB.x + mv.x, 30.0f));
                s[3] = ex2(fminf(s[3] + tB.y + mv.y, 30.0f));
                lrow0 += s[0] + s[1];
                lrow1 += s[2] + s[3];
            }
        }

        #pragma unroll
        for (int kc = 0; kc < 4; kc++) {
            uint32_t pa[4];
            {
                uint32_t t0 = f2tf(sacc[kc][0]);
                uint32_t t1 = f2tf(sacc[kc][1]);
                uint32_t t2 = f2tf(sacc[kc][2]);
                uint32_t t3 = f2tf(sacc[kc][3]);
                uint32_t e0 = __shfl_sync(~0u, t0, srcA), o0 = __shfl_sync(~0u, t1, srcA);
                uint32_t e1 = __shfl_sync(~0u, t2, srcA), o1 = __shfl_sync(~0u, t3, srcA);
                uint32_t e2 = __shfl_sync(~0u, t0, srcB), o2 = __shfl_sync(~0u, t1, srcB);
                uint32_t e3 = __shfl_sync(~0u, t2, srcB), o3 = __shfl_sync(~0u, t3, srcB);
                pa[0] = odd ? o0 : e0;
                pa[1] = odd ? o1 : e1;
                pa[2] = odd ? o2 : e2;
                pa[3] = odd ? o3 : e3;
            }
            int kk = kbase + kc * 8 + q4;
            #pragma unroll
            for (int dn = 0; dn < 4; dn++) {
                int dd = dn * 8 + r8;
                uint32_t b0 = BITS(Vsh[kk * VSTR + dd]);
                uint32_t b1 = BITS(Vsh[(kk + 4) * VSTR + dd]);
                mma8(oacc[dn], pa, b0, b1);
            }
        }
    }

    lrow0 += __shfl_xor_sync(~0u, lrow0, 1);
    lrow0 += __shfl_xor_sync(~0u, lrow0, 2);
    lrow1 += __shfl_xor_sync(~0u, lrow1, 1);
    lrow1 += __shfl_xor_sync(~0u, lrow1, 2);

    {
        float inv0 = 1.0f / fmaxf(lrow0, 1e-30f);
        float inv1 = 1.0f / fmaxf(lrow1, 1e-30f);
        size_t row0 = ((size_t)i * J_DIM + qbase + r8) * 128 + h * 32;
        size_t row1 = row0 + (size_t)8 * 128;
        #pragma unroll
        for (int dn = 0; dn < 4; dn++) {
            int c = dn * 8 + 2 * q4;
            float2 gv0 = *(const float2*)(g_g + row0 + c);
            float2 gv1 = *(const float2*)(g_g + row1 + c);
            *(float2*)(g_o + row0 + c) =
                make_float2(oacc[dn][0] * inv0 * gv0.x,
                            oacc[dn][1] * inv0 * gv0.y);
            *(float2*)(g_o + row1 + c) =
                make_float2(oacc[dn][2] * inv1 * gv1.x,
                            oacc[dn][3] * inv1 * gv1.y);
        }
    }
}

// ---------------- Kernel 3: output projection (tf32 MMA) ------------------
__global__ __launch_bounds__(256, 2) void out_kernel(
    const float* __restrict__ wo, const float* __restrict__ bo,
    float* __restrict__ out)
{
    extern __shared__ float sh[];
    float* As = sh;                 // [64][SA]
    float* Bs = sh + 64 * SA;       // [128][SB]

    int m0 = blockIdx.x * 64;
    int tid = threadIdx.x, wid = tid >> 5, lane = tid & 31;
    int warpM = (wid >> 2) * 32, warpN = (wid & 3) * 32;
    int q4 = lane & 3, r8 = lane >> 2;

    const float4* A4 = (const float4*)g_o + (size_t)m0 * 32;
    #pragma unroll
    for (int it = 0; it < 8; it++) {
        int idx = tid + it * 256;
        int rr = idx >> 5, c4 = idx & 31;
        float4 v = A4[idx];
        float* dst = As + rr * SA + c4 * 4;
        dst[0] = tf2f(v.x); dst[1] = tf2f(v.y); dst[2] = tf2f(v.z); dst[3] = tf2f(v.w);
    }
    const float4* W4 = (const float4*)wo;
    #pragma unroll
    for (int it = 0; it < 16; it++) {
        int idx = tid + it * 256;
        int kk = idx >> 5, c4 = idx & 31;
        float4 v = W4[idx];
        float* dst = Bs + kk * SB + c4 * 4;
        dst[0] = tf2f(v.x); dst[1] = tf2f(v.y); dst[2] = tf2f(v.z); dst[3] = tf2f(v.w);
    }
    __syncthreads();

    float acc[2][4][4];
    #pragma unroll
    for (int mt = 0; mt < 2; mt++)
        #pragma unroll
        for (int nt = 0; nt < 4; nt++)
            #pragma unroll
            for (int u = 0; u < 4; u++) acc[mt][nt][u] = 0.0f;

    MMA_MAINLOOP(acc)

    #pragma unroll
    for (int mt = 0; mt < 2; mt++) {
        int row0 = m0 + warpM + mt * 16 + r8;
        #pragma unroll
        for (int nt = 0; nt < 4; nt++) {
            int col = warpN + nt * 8 + 2 * q4;
            float b0v = bo[col], b1v = bo[col + 1];
            *(float2*)&out[(size_t)row0 * 128 + col] =
                make_float2(acc[mt][nt][0] + b0v, acc[mt][nt][1] + b1v);
            *(float2*)&out[(size_t)(row0 + 8) * 128 + col] =
                make_float2(acc[mt][nt][2] + b0v, acc[mt][nt][3] + b1v);
        }
    }
}

// ---------------- launch --------------------------------------------------
extern "C" void kernel_launch(void* const* d_in, const int* in_sizes, int n_in,
                              void* d_out, int out_size)
{
    const float* x     = (const float*)d_in[0];
    const float* mask  = (const float*)d_in[1];
    const float* ln_g  = (const float*)d_in[2];
    const float* ln_b  = (const float*)d_in[3];
    const float* w_tri = (const float*)d_in[4];
    const float* wq    = (const float*)d_in[5];
    const float* wk    = (const float*)d_in[6];
    const float* wv    = (const float*)d_in[7];
    const float* wg    = (const float*)d_in[8];
    const float* bg    = (const float*)d_in[9];
    const float* wo    = (const float*)d_in[10];
    const float* bo    = (const float*)d_in[11];
    float* out = (float*)d_out;

    const int SMEM_GEMM = (64 * SA + 128 * SB) * (int)sizeof(float);            // 103424
    const int SMEM_ATTN = (384 * KSTR + 384 * VSTR + 384) * (int)sizeof(float); // 118272
    cudaFuncSetAttribute(proj_kernel,
                         cudaFuncAttributeMaxDynamicSharedMemorySize, SMEM_GEMM);
    cudaFuncSetAttribute(out_kernel,
                         cudaFuncAttributeMaxDynamicSharedMemorySize, SMEM_GEMM);
    cudaFuncSetAttribute(attn_kernel,
                         cudaFuncAttributeMaxDynamicSharedMemorySize, SMEM_ATTN);

    proj_kernel<<<ROWS / 64, 256, SMEM_GEMM>>>(x, ln_g, ln_b, w_tri,
                                               wq, wk, wv, wg, bg);
    attn_kernel<<<dim3(I_DIM, H_DIM), 768, SMEM_ATTN>>>(mask);
    out_kernel<<<ROWS / 64, 256, SMEM_GEMM>>>(wo, bo, out);
}

// round 10
// speedup vs baseline: 2.2123x; 1.4706x over previous
#include <cuda_runtime.h>
#include <cuda_fp16.h>
#include <math.h>
#include <stdint.h>

#define I_DIM 384
#define J_DIM 384
#define C_DIM 128
#define H_DIM 4
#define ROWS (I_DIM * J_DIM)          // 147456
#define LN_EPS 1e-5f
#define LOG2E 1.4426950408889634f

// ---------------- scratch (fp16 halves traffic) ---------------------------
__device__ float  g_tri[H_DIM * ROWS];   // [h][q*384+k], pre-scaled by LOG2E
__device__ __half g_qh[ROWS * C_DIM];    // pre-scaled by (1/sqrt(32))*LOG2E
__device__ __half g_kh[ROWS * C_DIM];
__device__ __half g_vh[ROWS * C_DIM];
__device__ __half g_gh[ROWS * C_DIM];
__device__ __half g_oh[ROWS * C_DIM];

// ---------------- helpers -------------------------------------------------
__device__ __forceinline__ float ex2(float x) {
    float r; asm("ex2.approx.ftz.f32 %0, %1;" : "=f"(r) : "f"(x)); return r;
}
__device__ __forceinline__ uint32_t pack_h2(float lo, float hi) {
    __half2 h = __float22half2_rn(make_float2(lo, hi));
    return *reinterpret_cast<uint32_t*>(&h);
}
__device__ __forceinline__ uint32_t smaddr(const void* p) {
    return (uint32_t)__cvta_generic_to_shared(p);
}
__device__ __forceinline__ void ldsm4(uint32_t* r, uint32_t addr) {
    asm volatile("ldmatrix.sync.aligned.m8n8.x4.shared.b16 {%0,%1,%2,%3}, [%4];"
        : "=r"(r[0]), "=r"(r[1]), "=r"(r[2]), "=r"(r[3]) : "r"(addr));
}
__device__ __forceinline__ void ldsm4t(uint32_t* r, uint32_t addr) {
    asm volatile("ldmatrix.sync.aligned.m8n8.x4.trans.shared.b16 {%0,%1,%2,%3}, [%4];"
        : "=r"(r[0]), "=r"(r[1]), "=r"(r[2]), "=r"(r[3]) : "r"(addr));
}
__device__ __forceinline__ void mma16(float* c, const uint32_t* a,
                                      uint32_t b0, uint32_t b1) {
    asm volatile(
        "mma.sync.aligned.m16n8k16.row.col.f32.f16.f16.f32 "
        "{%0,%1,%2,%3},{%4,%5,%6,%7},{%8,%9},{%0,%1,%2,%3};"
        : "+f"(c[0]), "+f"(c[1]), "+f"(c[2]), "+f"(c[3])
        : "r"(a[0]), "r"(a[1]), "r"(a[2]), "r"(a[3]), "r"(b0), "r"(b1));
}

#define SA32 132   // fp32 LN staging stride
#define SAH  136   // fp16 A stride: 272B rows -> 8 LDSM rows hit distinct 16B banks
#define SBH  136   // fp16 B stride

// ---------------- Kernel 1: fused LN + tri + q/k/v/g projection -----------
__global__ __launch_bounds__(256, 2) void proj_kernel(
    const float* __restrict__ x,
    const float* __restrict__ ln_g, const float* __restrict__ ln_b,
    const float* __restrict__ w_tri,
    const float* __restrict__ wq, const float* __restrict__ wk,
    const float* __restrict__ wv, const float* __restrict__ wg,
    const float* __restrict__ bg)
{
    extern __shared__ float sh[];
    float*  As32 = sh;                              // [64][132] fp32
    __half* As16 = (__half*)(sh + 64 * SA32);       // [64][136] fp16
    __half* Bs16 = As16 + 64 * SAH;                 // [128][136] fp16

    int m0 = blockIdx.x * 64;
    int tid = threadIdx.x, wid = tid >> 5, lane = tid & 31;
    int warpM = (wid >> 2) * 32, warpN = (wid & 3) * 32;
    int q4 = lane & 3, r8 = lane >> 2;

    // ---- stage raw x (coalesced) ----
    const float4* X4 = (const float4*)x + (size_t)m0 * 32;
    #pragma unroll
    for (int it = 0; it < 8; it++) {
        int idx = tid + it * 256;
        int rr = idx >> 5, c4 = idx & 31;
        *(float4*)(As32 + rr * SA32 + c4 * 4) = X4[idx];
    }
    __syncthreads();

    // ---- LayerNorm + tri bias; write fp16 tile ----
    {
        int row = tid >> 2, qq = tid & 3;
        const float* rp = As32 + row * SA32 + qq * 32;
        __half* rp16 = As16 + row * SAH + qq * 32;
        float vals[32];
        float sum = 0.0f, ss = 0.0f;
        #pragma unroll
        for (int j = 0; j < 32; j++) {
            float v = rp[j];
            vals[j] = v; sum += v; ss += v * v;
        }
        sum += __shfl_xor_sync(~0u, sum, 1);
        sum += __shfl_xor_sync(~0u, sum, 2);
        ss  += __shfl_xor_sync(~0u, ss, 1);
        ss  += __shfl_xor_sync(~0u, ss, 2);
        float mean = sum * (1.0f / 128.0f);
        float var  = ss * (1.0f / 128.0f) - mean * mean;
        float rstd = rsqrtf(var + LN_EPS);

        const float4* G4 = (const float4*)ln_g + qq * 8;
        const float4* B4 = (const float4*)ln_b + qq * 8;
        const float4* W4 = (const float4*)w_tri + qq * 32;
        float p0 = 0.0f, p1 = 0.0f, p2 = 0.0f, p3 = 0.0f;
        #pragma unroll
        for (int j4 = 0; j4 < 8; j4++) {
            float4 gg = G4[j4], bb = B4[j4];
            float xn0 = (vals[4*j4+0] - mean) * rstd * gg.x + bb.x;
            float xn1 = (vals[4*j4+1] - mean) * rstd * gg.y + bb.y;
            float xn2 = (vals[4*j4+2] - mean) * rstd * gg.z + bb.z;
            float xn3 = (vals[4*j4+3] - mean) * rstd * gg.w + bb.w;
            *(uint32_t*)&rp16[4*j4+0] = pack_h2(xn0, xn1);
            *(uint32_t*)&rp16[4*j4+2] = pack_h2(xn2, xn3);
            float4 w0 = W4[4*j4+0], w1 = W4[4*j4+1];
            float4 w2 = W4[4*j4+2], w3 = W4[4*j4+3];
            p0 += xn0*w0.x + xn1*w1.x + xn2*w2.x + xn3*w3.x;
            p1 += xn0*w0.y + xn1*w1.y + xn2*w2.y + xn3*w3.y;
            p2 += xn0*w0.z + xn1*w1.z + xn2*w2.z + xn3*w3.z;
            p3 += xn0*w0.w + xn1*w1.w + xn2*w2.w + xn3*w3.w;
        }
        #pragma unroll
        for (int o = 1; o <= 2; o <<= 1) {
            p0 += __shfl_xor_sync(~0u, p0, o);
            p1 += __shfl_xor_sync(~0u, p1, o);
            p2 += __shfl_xor_sync(~0u, p2, o);
            p3 += __shfl_xor_sync(~0u, p3, o);
        }
        float pv = (qq == 0) ? p0 : (qq == 1) ? p1 : (qq == 2) ? p2 : p3;
        g_tri[(size_t)qq * ROWS + m0 + row] = pv * LOG2E;
    }

    // ldmatrix lane base addresses
    int L = lane;
    uint32_t aAddr = smaddr(As16 + (warpM + (L & 7) + ((L >> 3) & 1) * 8) * SAH
                                 + (L >> 4) * 8);
    uint32_t bAddr = smaddr(Bs16 + ((L & 7) + ((L >> 3) & 1) * 8) * SBH
                                 + warpN + (L >> 4) * 8);

    // ---- 4 weight GEMMs ----
    #pragma unroll 1
    for (int y = 0; y < 4; y++) {
        const float* W = (y == 0) ? wq : (y == 1) ? wk : (y == 2) ? wv : wg;
        __half*      O = (y == 0) ? g_qh : (y == 1) ? g_kh : (y == 2) ? g_vh : g_gh;

        __syncthreads();          // LN writes (y=0) / prior frag reads done
        const float4* W4 = (const float4*)W;
        #pragma unroll
        for (int it = 0; it < 16; it++) {
            int idx = tid + it * 256;
            int kk = idx >> 5, c4 = idx & 31;
            float4 v = W4[idx];
            *(uint2*)&Bs16[kk * SBH + c4 * 4] =
                make_uint2(pack_h2(v.x, v.y), pack_h2(v.z, v.w));
        }
        __syncthreads();

        float acc[2][4][4];
        #pragma unroll
        for (int mt = 0; mt < 2; mt++)
            #pragma unroll
            for (int nt = 0; nt < 4; nt++)
                #pragma unroll
                for (int u = 0; u < 4; u++) acc[mt][nt][u] = 0.0f;

        #pragma unroll
        for (int kc = 0; kc < 8; kc++) {
            uint32_t a0[4], a1[4], b0[4], b1[4];
            ldsm4 (a0, aAddr + kc * 32);                      // mt0, k16 chunk
            ldsm4 (a1, aAddr + kc * 32 + 16 * SAH * 2);       // mt1
            ldsm4t(b0, bAddr + kc * 16 * SBH * 2);            // n-blocks 0,1
            ldsm4t(b1, bAddr + kc * 16 * SBH * 2 + 32);       // n-blocks 2,3
            mma16(acc[0][0], a0, b0[0], b0[1]);
            mma16(acc[0][1], a0, b0[2], b0[3]);
            mma16(acc[0][2], a0, b1[0], b1[1]);
            mma16(acc[0][3], a0, b1[2], b1[3]);
            mma16(acc[1][0], a1, b0[0], b0[1]);
            mma16(acc[1][1], a1, b0[2], b0[3]);
            mma16(acc[1][2], a1, b1[0], b1[1]);
            mma16(acc[1][3], a1, b1[2], b1[3]);
        }

        const float qscale = 0.17677669529663687f * LOG2E;
        #pragma unroll
        for (int mt = 0; mt < 2; mt++) {
            int row0 = m0 + warpM + mt * 16 + r8;
            #pragma unroll
            for (int nt = 0; nt < 4; nt++) {
                int col = warpN + nt * 8 + 2 * q4;
                float v0 = acc[mt][nt][0], v1 = acc[mt][nt][1];
                float v2 = acc[mt][nt][2], v3 = acc[mt][nt][3];
                if (y == 0) { v0 *= qscale; v1 *= qscale; v2 *= qscale; v3 *= qscale; }
                if (y == 3) {
                    float b0v = bg[col], b1v = bg[col + 1];
                    v0 = 1.0f / (1.0f + __expf(-(v0 + b0v)));
                    v1 = 1.0f / (1.0f + __expf(-(v1 + b1v)));
                    v2 = 1.0f / (1.0f + __expf(-(v2 + b0v)));
                    v3 = 1.0f / (1.0f + __expf(-(v3 + b1v)));
                }
                *(uint32_t*)&O[(size_t)row0 * 128 + col]       = pack_h2(v0, v1);
                *(uint32_t*)&O[(size_t)(row0 + 8) * 128 + col] = pack_h2(v2, v3);
            }
        }
    }
}

// ---------------- Kernel 2: fp16 MMA flash attention ----------------------
// block (i,h), 768 threads = 24 warps x 16 query rows. Fixed-shift softmax.
// P-fragment conversion is pure cvt+pack (C-frag layout == A-frag layout).
#define KVS 40    // K/V smem stride (fp16): 80B rows -> LDSM conflict-free

__global__ __launch_bounds__(768) void attn_kernel(const float* __restrict__ mask)
{
    extern __shared__ float sh[];
    __half* Ksh = (__half*)sh;                 // [384][40]
    __half* Vsh = Ksh + 384 * KVS;             // [384][40]
    float*  mb  = (float*)(Vsh + 384 * KVS);   // [384]

    int i = blockIdx.x, h = blockIdx.y;
    int tid = threadIdx.x, wid = tid >> 5, lane = tid & 31;
    int q4 = lane & 3, r8 = lane >> 2;

    // ---- stage K,V (fp16 -> fp16, uint4 = 8 halves) ----
    const uint4* K4 = (const uint4*)(g_kh + (size_t)i * J_DIM * 128 + h * 32);
    const uint4* V4 = (const uint4*)(g_vh + (size_t)i * J_DIM * 128 + h * 32);
    #pragma unroll
    for (int it = 0; it < 2; it++) {
        int idx = tid + it * 768;            // 0..1535 uint4s
        int j = idx >> 2, c8 = idx & 3;      // row stride 128 halves = 16 uint4
        *(uint4*)(Ksh + j * KVS + c8 * 8) = K4[(size_t)j * 16 + c8];
        *(uint4*)(Vsh + j * KVS + c8 * 8) = V4[(size_t)j * 16 + c8];
    }
    if (tid < 384)
        mb[tid] = (LOG2E * 1.0e9f) * (mask[(size_t)i * J_DIM + tid] - 1.0f);
    __syncthreads();

    int qbase = wid * 16;
    // Q A-frags straight from gmem (fp16 pairs are 4B loads)
    uint32_t qa[2][4];
    {
        const __half* Qp = g_qh + ((size_t)i * J_DIM + qbase) * 128 + h * 32;
        #pragma unroll
        for (int dc = 0; dc < 2; dc++) {
            const __half* Qk = Qp + dc * 16;
            qa[dc][0] = *(const uint32_t*)&Qk[r8 * 128 + 2 * q4];
            qa[dc][1] = *(const uint32_t*)&Qk[(r8 + 8) * 128 + 2 * q4];
            qa[dc][2] = *(const uint32_t*)&Qk[r8 * 128 + 2 * q4 + 8];
            qa[dc][3] = *(const uint32_t*)&Qk[(r8 + 8) * 128 + 2 * q4 + 8];
        }
    }

    float oacc[4][4];
    #pragma unroll
    for (int dn = 0; dn < 4; dn++)
        #pragma unroll
        for (int u = 0; u < 4; u++) oacc[dn][u] = 0.0f;
    float lrow0 = 0.0f, lrow1 = 0.0f;

    const float* triW = g_tri + (size_t)h * ROWS;
    int L = lane;
    // K (non-trans): matrices = (key-block, d-chunk): row=key, col=d
    uint32_t kAddr = smaddr(Ksh + (((L >> 4) & 1) * 8 + (L & 7)) * KVS
                                + ((L >> 3) & 1) * 8);
    // V (trans): matrices = (key-chunk k, d-block n): row=key, col=d
    uint32_t vAddr = smaddr(Vsh + ((L & 7) + ((L >> 3) & 1) * 8) * KVS
                                + (L >> 4) * 8);

    #pragma unroll 1
    for (int kb = 0; kb < 12; kb++) {
        int kbase = kb * 32;
        uint32_t kbB = (uint32_t)kbase * (KVS * 2);   // byte offset of key rows

        // ---- S = Q K^T (16 rows x 32 keys) ----
        float sacc[4][4];
        #pragma unroll
        for (int nt = 0; nt < 4; nt++)
            #pragma unroll
            for (int u = 0; u < 4; u++) sacc[nt][u] = 0.0f;

        #pragma unroll
        for (int dc = 0; dc < 2; dc++) {
            uint32_t b0[4], b1[4];
            ldsm4(b0, kAddr + kbB + dc * 32);                   // keys 0..15
            ldsm4(b1, kAddr + kbB + 16 * KVS * 2 + dc * 32);    // keys 16..31
            mma16(sacc[0], qa[dc], b0[0], b0[1]);
            mma16(sacc[1], qa[dc], b0[2], b0[3]);
            mma16(sacc[2], qa[dc], b1[0], b1[1]);
            mma16(sacc[3], qa[dc], b1[2], b1[3]);
        }

        // ---- bias + fixed-shift exp2 (no online max, no shuffles) ----
        {
            int qrow = qbase + r8;
            const float* t0p = triW + (size_t)qrow * J_DIM + kbase + 2 * q4;
            const float* t1p = t0p + 8 * J_DIM;
            #pragma unroll
            for (int nt = 0; nt < 4; nt++) {
                float2 tA = *(const float2*)(t0p + nt * 8);
                float2 tB = *(const float2*)(t1p + nt * 8);
                float2 mv = *(const float2*)(mb + kbase + nt * 8 + 2 * q4);
                float* s = sacc[nt];
                s[0] = ex2(fminf(s[0] + tA.x + mv.x, 15.0f));
                s[1] = ex2(fminf(s[1] + tA.y + mv.y, 15.0f));
                s[2] = ex2(fminf(s[2] + tB.x + mv.x, 15.0f));
                s[3] = ex2(fminf(s[3] + tB.y + mv.y, 15.0f));
                lrow0 += s[0] + s[1];
                lrow1 += s[2] + s[3];
            }
        }

        // ---- O += P V  (P: cvt+pack only — layouts match) ----
        #pragma unroll
        for (int kc = 0; kc < 2; kc++) {
            uint32_t pa[4];
            pa[0] = pack_h2(sacc[2*kc][0],   sacc[2*kc][1]);
            pa[1] = pack_h2(sacc[2*kc][2],   sacc[2*kc][3]);
            pa[2] = pack_h2(sacc[2*kc+1][0], sacc[2*kc+1][1]);
            pa[3] = pack_h2(sacc[2*kc+1][2], sacc[2*kc+1][3]);

            uint32_t vb0[4], vb1[4];
            uint32_t vOff = kbB + (uint32_t)kc * 16 * KVS * 2;
            ldsm4t(vb0, vAddr + vOff);            // d-blocks 0,1
            ldsm4t(vb1, vAddr + vOff + 32);       // d-blocks 2,3
            mma16(oacc[0], pa, vb0[0], vb0[1]);
            mma16(oacc[1], pa, vb0[2], vb0[3]);
            mma16(oacc[2], pa, vb1[0], vb1[1]);
            mma16(oacc[3], pa, vb1[2], vb1[3]);
        }
    }

    // ---- final l reduction (once) ----
    lrow0 += __shfl_xor_sync(~0u, lrow0, 1);
    lrow0 += __shfl_xor_sync(~0u, lrow0, 2);
    lrow1 += __shfl_xor_sync(~0u, lrow1, 1);
    lrow1 += __shfl_xor_sync(~0u, lrow1, 2);

    // ---- finalize: 1/l, gate, store fp16 ----
    {
        float inv0 = 1.0f / fmaxf(lrow0, 1e-30f);
        float inv1 = 1.0f / fmaxf(lrow1, 1e-30f);
        size_t row0 = ((size_t)i * J_DIM + qbase + r8) * 128 + h * 32;
        size_t row1 = row0 + (size_t)8 * 128;
        #pragma unroll
        for (int dn = 0; dn < 4; dn++) {
            int c = dn * 8 + 2 * q4;
            __half2 gh0 = *(const __half2*)&g_gh[row0 + c];
            __half2 gh1 = *(const __half2*)&g_gh[row1 + c];
            float2 gv0 = __half22float2(gh0);
            float2 gv1 = __half22float2(gh1);
            *(uint32_t*)&g_oh[row0 + c] =
                pack_h2(oacc[dn][0] * inv0 * gv0.x, oacc[dn][1] * inv0 * gv0.y);
            *(uint32_t*)&g_oh[row1 + c] =
                pack_h2(oacc[dn][2] * inv1 * gv1.x, oacc[dn][3] * inv1 * gv1.y);
        }
    }
}

// ---------------- Kernel 3: output projection (fp16 MMA) ------------------
__global__ __launch_bounds__(256, 2) void out_kernel(
    const float* __restrict__ wo, const float* __restrict__ bo,
    float* __restrict__ out)
{
    extern __shared__ float sh[];
    __half* As16 = (__half*)sh;          // [64][136]
    __half* Bs16 = As16 + 64 * SAH;      // [128][136]

    int m0 = blockIdx.x * 64;
    int tid = threadIdx.x, wid = tid >> 5, lane = tid & 31;
    int warpM = (wid >> 2) * 32, warpN = (wid & 3) * 32;
    int q4 = lane & 3, r8 = lane >> 2;

    // stage A (already fp16) — uint4 = 8 halves
    const uint4* A4 = (const uint4*)(g_oh + (size_t)m0 * 128);
    #pragma unroll
    for (int it = 0; it < 4; it++) {
        int idx = tid + it * 256;            // 0..1023 uint4s
        int rr = idx >> 4, c8 = idx & 15;
        *(uint4*)(As16 + rr * SAH + c8 * 8) = A4[idx];
    }
    // stage B (fp32 -> fp16)
    const float4* W4 = (const float4*)wo;
    #pragma unroll
    for (int it = 0; it < 16; it++) {
        int idx = tid + it * 256;
        int kk = idx >> 5, c4 = idx & 31;
        float4 v = W4[idx];
        *(uint2*)&Bs16[kk * SBH + c4 * 4] =
            make_uint2(pack_h2(v.x, v.y), pack_h2(v.z, v.w));
    }
    __syncthreads();

    int L = lane;
    uint32_t aAddr = smaddr(As16 + (warpM + (L & 7) + ((L >> 3) & 1) * 8) * SAH
                                 + (L >> 4) * 8);
    uint32_t bAddr = smaddr(Bs16 + ((L & 7) + ((L >> 3) & 1) * 8) * SBH
                                 + warpN + (L >> 4) * 8);

    float acc[2][4][4];
    #pragma unroll
    for (int mt = 0; mt < 2; mt++)
        #pragma unroll
        for (int nt = 0; nt < 4; nt++)
            #pragma unroll
            for (int u = 0; u < 4; u++) acc[mt][nt][u] = 0.0f;

    #pragma unroll
    for (int kc = 0; kc < 8; kc++) {
        uint32_t a0[4], a1[4], b0[4], b1[4];
        ldsm4 (a0, aAddr + kc * 32);
        ldsm4 (a1, aAddr + kc * 32 + 16 * SAH * 2);
        ldsm4t(b0, bAddr + kc * 16 * SBH * 2);
        ldsm4t(b1, bAddr + kc * 16 * SBH * 2 + 32);
        mma16(acc[0][0], a0, b0[0], b0[1]);
        mma16(acc[0][1], a0, b0[2], b0[3]);
        mma16(acc[0][2], a0, b1[0], b1[1]);
        mma16(acc[0][3], a0, b1[2], b1[3]);
        mma16(acc[1][0], a1, b0[0], b0[1]);
        mma16(acc[1][1], a1, b0[2], b0[3]);
        mma16(acc[1][2], a1, b1[0], b1[1]);
        mma16(acc[1][3], a1, b1[2], b1[3]);
    }

    #pragma unroll
    for (int mt = 0; mt < 2; mt++) {
        int row0 = m0 + warpM + mt * 16 + r8;
        #pragma unroll
        for (int nt = 0; nt < 4; nt++) {
            int col = warpN + nt * 8 + 2 * q4;
            float b0v = bo[col], b1v = bo[col + 1];
            *(float2*)&out[(size_t)row0 * 128 + col] =
                make_float2(acc[mt][nt][0] + b0v, acc[mt][nt][1] + b1v);
            *(float2*)&out[(size_t)(row0 + 8) * 128 + col] =
                make_float2(acc[mt][nt][2] + b0v, acc[mt][nt][3] + b1v);
        }
    }
}

// ---------------- launch ---------------------------------------------------
extern "C" void kernel_launch(void* const* d_in, const int* in_sizes, int n_in,
                              void* d_out, int out_size)
{
    const float* x     = (const float*)d_in[0];
    const float* mask  = (const float*)d_in[1];
    const float* ln_g  = (const float*)d_in[2];
    const float* ln_b  = (const float*)d_in[3];
    const float* w_tri = (const float*)d_in[4];
    const float* wq    = (const float*)d_in[5];
    const float* wk    = (const float*)d_in[6];
    const float* wv    = (const float*)d_in[7];
    const float* wg    = (const float*)d_in[8];
    const float* bg    = (const float*)d_in[9];
    const float* wo    = (const float*)d_in[10];
    const float* bo    = (const float*)d_in[11];
    float* out = (float*)d_out;

    const int SMEM_PROJ = 64 * SA32 * 4 + 64 * SAH * 2 + 128 * SBH * 2;   // 86016
    const int SMEM_OUT  = 64 * SAH * 2 + 128 * SBH * 2;                   // 52224
    const int SMEM_ATTN = 2 * 384 * KVS * 2 + 384 * 4;                    // 62976
    cudaFuncSetAttribute(proj_kernel,
                         cudaFuncAttributeMaxDynamicSharedMemorySize, SMEM_PROJ);
    cudaFuncSetAttribute(out_kernel,
                         cudaFuncAttributeMaxDynamicSharedMemorySize, SMEM_OUT);
    cudaFuncSetAttribute(attn_kernel,
                         cudaFuncAttributeMaxDynamicSharedMemorySize, SMEM_ATTN);

    proj_kernel<<<ROWS / 64, 256, SMEM_PROJ>>>(x, ln_g, ln_b, w_tri,
                                               wq, wk, wv, wg, bg);
    attn_kernel<<<dim3(I_DIM, H_DIM), 768, SMEM_ATTN>>>(mask);
    out_kernel<<<ROWS / 64, 256, SMEM_OUT>>>(wo, bo, out);
}

// round 11
// speedup vs baseline: 2.3875x; 1.0792x over previous
#include <cuda_runtime.h>
#include <cuda_fp16.h>
#include <math.h>
#include <stdint.h>

#define I_DIM 384
#define J_DIM 384
#define C_DIM 128
#define H_DIM 4
#define ROWS (I_DIM * J_DIM)          // 147456
#define LN_EPS 1e-5f
#define LOG2E 1.4426950408889634f

// ---------------- scratch -------------------------------------------------
__device__ __half g_trih[H_DIM * ROWS];  // [h][q*384+k], pre-scaled by LOG2E
__device__ __half g_qh[ROWS * C_DIM];    // pre-scaled by (1/sqrt(32))*LOG2E
__device__ __half g_kh[ROWS * C_DIM];
__device__ __half g_vh[ROWS * C_DIM];
__device__ __half g_gh[ROWS * C_DIM];
__device__ __half g_oh[ROWS * C_DIM];
__device__ __half g_wh[4][C_DIM * C_DIM];   // wq wk wv wg (fp16)
__device__ __half g_woh[C_DIM * C_DIM];     // wo (fp16)

// ---------------- helpers -------------------------------------------------
__device__ __forceinline__ float ex2(float x) {
    float r; asm("ex2.approx.ftz.f32 %0, %1;" : "=f"(r) : "f"(x)); return r;
}
__device__ __forceinline__ uint32_t pack_h2(float lo, float hi) {
    __half2 h = __float22half2_rn(make_float2(lo, hi));
    return *reinterpret_cast<uint32_t*>(&h);
}
__device__ __forceinline__ uint32_t smaddr(const void* p) {
    return (uint32_t)__cvta_generic_to_shared(p);
}
__device__ __forceinline__ void ldsm4(uint32_t* r, uint32_t addr) {
    asm volatile("ldmatrix.sync.aligned.m8n8.x4.shared.b16 {%0,%1,%2,%3}, [%4];"
        : "=r"(r[0]), "=r"(r[1]), "=r"(r[2]), "=r"(r[3]) : "r"(addr));
}
__device__ __forceinline__ void ldsm4t(uint32_t* r, uint32_t addr) {
    asm volatile("ldmatrix.sync.aligned.m8n8.x4.trans.shared.b16 {%0,%1,%2,%3}, [%4];"
        : "=r"(r[0]), "=r"(r[1]), "=r"(r[2]), "=r"(r[3]) : "r"(addr));
}
__device__ __forceinline__ void mma16(float* c, const uint32_t* a,
                                      uint32_t b0, uint32_t b1) {
    asm volatile(
        "mma.sync.aligned.m16n8k16.row.col.f32.f16.f16.f32 "
        "{%0,%1,%2,%3},{%4,%5,%6,%7},{%8,%9},{%0,%1,%2,%3};"
        : "+f"(c[0]), "+f"(c[1]), "+f"(c[2]), "+f"(c[3])
        : "r"(a[0]), "r"(a[1]), "r"(a[2]), "r"(a[3]), "r"(b0), "r"(b1));
}

#define SAH 136   // fp16 A stride
#define SBH 136   // fp16 B stride
#define SEF 136   // fp32 epilogue stride (out_kernel)

// ---------------- Kernel 0: one-time fp32 -> fp16 weight conversion -------
__global__ __launch_bounds__(256) void cvt_kernel(
    const float* __restrict__ wq, const float* __restrict__ wk,
    const float* __restrict__ wv, const float* __restrict__ wg,
    const float* __restrict__ wo)
{
    int idx = blockIdx.x * 256 + threadIdx.x;      // 0..4095 float4 units
    const float* srcs[5] = {wq, wk, wv, wg, wo};
    __half* dsts[5] = {g_wh[0], g_wh[1], g_wh[2], g_wh[3], g_woh};
    #pragma unroll
    for (int m = 0; m < 5; m++) {
        float4 v = ((const float4*)srcs[m])[idx];
        ((uint2*)dsts[m])[idx] =
            make_uint2(pack_h2(v.x, v.y), pack_h2(v.z, v.w));
    }
}

// ---------------- Kernel 1: fused LN + tri + q/k/v/g projection -----------
// LN loads x straight into registers (no fp32 staging tile). smem = 52 KB.
__global__ __launch_bounds__(256, 3) void proj_kernel(
    const float* __restrict__ x,
    const float* __restrict__ ln_g, const float* __restrict__ ln_b,
    const float* __restrict__ w_tri, const float* __restrict__ bg)
{
    extern __shared__ __half shh[];
    __half* As16 = shh;                  // [64][SAH]
    __half* Bs16 = As16 + 64 * SAH;      // [128][SBH]; reused as epilogue tile

    int m0 = blockIdx.x * 64;
    int tid = threadIdx.x, wid = tid >> 5, lane = tid & 31;
    int warpM = (wid >> 2) * 32, warpN = (wid & 3) * 32;
    int q4 = lane & 3, r8 = lane >> 2;

    // ---- LayerNorm + tri: thread = (row, quarter); coalesced LDG.128 ----
    {
        int row = tid >> 2, qq = tid & 3;
        const float4* xp = (const float4*)(x + ((size_t)(m0 + row)) * 128 + qq * 32);
        float vals[32];
        float sum = 0.0f, ss = 0.0f;
        #pragma unroll
        for (int j4 = 0; j4 < 8; j4++) {
            float4 v = xp[j4];
            vals[4*j4+0] = v.x; vals[4*j4+1] = v.y;
            vals[4*j4+2] = v.z; vals[4*j4+3] = v.w;
            sum += v.x + v.y + v.z + v.w;
            ss  += v.x*v.x + v.y*v.y + v.z*v.z + v.w*v.w;
        }
        sum += __shfl_xor_sync(~0u, sum, 1);
        sum += __shfl_xor_sync(~0u, sum, 2);
        ss  += __shfl_xor_sync(~0u, ss, 1);
        ss  += __shfl_xor_sync(~0u, ss, 2);
        float mean = sum * (1.0f / 128.0f);
        float var  = ss * (1.0f / 128.0f) - mean * mean;
        float rstd = rsqrtf(var + LN_EPS);

        __half* rp16 = As16 + row * SAH + qq * 32;
        const float4* G4 = (const float4*)ln_g + qq * 8;
        const float4* B4 = (const float4*)ln_b + qq * 8;
        const float4* W4 = (const float4*)w_tri + qq * 32;
        float p0 = 0.0f, p1 = 0.0f, p2 = 0.0f, p3 = 0.0f;
        #pragma unroll
        for (int j4 = 0; j4 < 8; j4++) {
            float4 gg = G4[j4], bb = B4[j4];
            float xn0 = (vals[4*j4+0] - mean) * rstd * gg.x + bb.x;
            float xn1 = (vals[4*j4+1] - mean) * rstd * gg.y + bb.y;
            float xn2 = (vals[4*j4+2] - mean) * rstd * gg.z + bb.z;
            float xn3 = (vals[4*j4+3] - mean) * rstd * gg.w + bb.w;
            *(uint32_t*)&rp16[4*j4+0] = pack_h2(xn0, xn1);
            *(uint32_t*)&rp16[4*j4+2] = pack_h2(xn2, xn3);
            float4 w0 = W4[4*j4+0], w1 = W4[4*j4+1];
            float4 w2 = W4[4*j4+2], w3 = W4[4*j4+3];
            p0 += xn0*w0.x + xn1*w1.x + xn2*w2.x + xn3*w3.x;
            p1 += xn0*w0.y + xn1*w1.y + xn2*w2.y + xn3*w3.y;
            p2 += xn0*w0.z + xn1*w1.z + xn2*w2.z + xn3*w3.z;
            p3 += xn0*w0.w + xn1*w1.w + xn2*w2.w + xn3*w3.w;
        }
        #pragma unroll
        for (int o = 1; o <= 2; o <<= 1) {
            p0 += __shfl_xor_sync(~0u, p0, o);
            p1 += __shfl_xor_sync(~0u, p1, o);
            p2 += __shfl_xor_sync(~0u, p2, o);
            p3 += __shfl_xor_sync(~0u, p3, o);
        }
        float pv = (qq == 0) ? p0 : (qq == 1) ? p1 : (qq == 2) ? p2 : p3;
        g_trih[(size_t)qq * ROWS + m0 + row] = __float2half(pv * LOG2E);
    }

    int L = lane;
    uint32_t aAddr = smaddr(As16 + (warpM + (L & 7) + ((L >> 3) & 1) * 8) * SAH
                                 + (L >> 4) * 8);
    uint32_t bAddr = smaddr(Bs16 + ((L & 7) + ((L >> 3) & 1) * 8) * SBH
                                 + warpN + (L >> 4) * 8);

    // ---- 4 weight GEMMs ----
    #pragma unroll 1
    for (int y = 0; y < 4; y++) {
        __half* O = (y == 0) ? g_qh : (y == 1) ? g_kh : (y == 2) ? g_vh : g_gh;

        __syncthreads();   // LN writes (y=0) / prior epilogue reads done
        const uint4* Wh = (const uint4*)g_wh[y];     // fp16: plain copy
        #pragma unroll
        for (int it = 0; it < 8; it++) {
            int idx = tid + it * 256;                // 0..2047 uint4s
            int kk = idx >> 4, c8 = idx & 15;
            *(uint4*)&Bs16[kk * SBH + c8 * 8] = Wh[idx];
        }
        __syncthreads();

        float acc[2][4][4];
        #pragma unroll
        for (int mt = 0; mt < 2; mt++)
            #pragma unroll
            for (int nt = 0; nt < 4; nt++)
                #pragma unroll
                for (int u = 0; u < 4; u++) acc[mt][nt][u] = 0.0f;

        #pragma unroll
        for (int kc = 0; kc < 8; kc++) {
            uint32_t a0[4], a1[4], b0[4], b1[4];
            ldsm4 (a0, aAddr + kc * 32);
            ldsm4 (a1, aAddr + kc * 32 + 16 * SAH * 2);
            ldsm4t(b0, bAddr + kc * 16 * SBH * 2);
            ldsm4t(b1, bAddr + kc * 16 * SBH * 2 + 32);
            mma16(acc[0][0], a0, b0[0], b0[1]);
            mma16(acc[0][1], a0, b0[2], b0[3]);
            mma16(acc[0][2], a0, b1[0], b1[1]);
            mma16(acc[0][3], a0, b1[2], b1[3]);
            mma16(acc[1][0], a1, b0[0], b0[1]);
            mma16(acc[1][1], a1, b0[2], b0[3]);
            mma16(acc[1][2], a1, b1[0], b1[1]);
            mma16(acc[1][3], a1, b1[2], b1[3]);
        }

        // ---- epilogue via smem: conflict-free STS, coalesced STG ----
        __syncthreads();                 // all Bs16 frag reads complete
        __half* Es = Bs16;               // [64][SBH] staging
        const float qscale = 0.17677669529663687f * LOG2E;
        #pragma unroll
        for (int mt = 0; mt < 2; mt++) {
            int r0 = warpM + mt * 16 + r8;
            #pragma unroll
            for (int nt = 0; nt < 4; nt++) {
                int col = warpN + nt * 8 + 2 * q4;
                float v0 = acc[mt][nt][0], v1 = acc[mt][nt][1];
                float v2 = acc[mt][nt][2], v3 = acc[mt][nt][3];
                if (y == 0) { v0 *= qscale; v1 *= qscale; v2 *= qscale; v3 *= qscale; }
                if (y == 3) {
                    float b0v = bg[col], b1v = bg[col + 1];
                    v0 = 1.0f / (1.0f + __expf(-(v0 + b0v)));
                    v1 = 1.0f / (1.0f + __expf(-(v1 + b1v)));
                    v2 = 1.0f / (1.0f + __expf(-(v2 + b0v)));
                    v3 = 1.0f / (1.0f + __expf(-(v3 + b1v)));
                }
                *(uint32_t*)&Es[r0 * SBH + col]       = pack_h2(v0, v1);
                *(uint32_t*)&Es[(r0 + 8) * SBH + col] = pack_h2(v2, v3);
            }
        }
        __syncthreads();
        uint4* O4 = (uint4*)(O + (size_t)m0 * 128);
        #pragma unroll
        for (int it = 0; it < 4; it++) {
            int idx = tid + it * 256;                // 0..1023 uint4s
            int rr = idx >> 4, c8 = idx & 15;
            O4[idx] = *(uint4*)&Es[rr * SBH + c8 * 8];
        }
    }
}

// ---------------- Kernel 2: fp16 MMA flash attention ----------------------
#define KVS 40

__global__ __launch_bounds__(768) void attn_kernel(const float* __restrict__ mask)
{
    extern __shared__ float sh[];
    __half* Ksh = (__half*)sh;                 // [384][40]
    __half* Vsh = Ksh + 384 * KVS;             // [384][40]
    float*  mb  = (float*)(Vsh + 384 * KVS);   // [384]

    int i = blockIdx.x, h = blockIdx.y;
    int tid = threadIdx.x, wid = tid >> 5, lane = tid & 31;
    int q4 = lane & 3, r8 = lane >> 2;

    const uint4* K4 = (const uint4*)(g_kh + (size_t)i * J_DIM * 128 + h * 32);
    const uint4* V4 = (const uint4*)(g_vh + (size_t)i * J_DIM * 128 + h * 32);
    #pragma unroll
    for (int it = 0; it < 2; it++) {
        int idx = tid + it * 768;
        int j = idx >> 2, c8 = idx & 3;
        *(uint4*)(Ksh + j * KVS + c8 * 8) = K4[(size_t)j * 16 + c8];
        *(uint4*)(Vsh + j * KVS + c8 * 8) = V4[(size_t)j * 16 + c8];
    }
    if (tid < 384)
        mb[tid] = (LOG2E * 1.0e9f) * (mask[(size_t)i * J_DIM + tid] - 1.0f);
    __syncthreads();

    int qbase = wid * 16;
    uint32_t qa[2][4];
    {
        const __half* Qp = g_qh + ((size_t)i * J_DIM + qbase) * 128 + h * 32;
        #pragma unroll
        for (int dc = 0; dc < 2; dc++) {
            const __half* Qk = Qp + dc * 16;
            qa[dc][0] = *(const uint32_t*)&Qk[r8 * 128 + 2 * q4];
            qa[dc][1] = *(const uint32_t*)&Qk[(r8 + 8) * 128 + 2 * q4];
            qa[dc][2] = *(const uint32_t*)&Qk[r8 * 128 + 2 * q4 + 8];
            qa[dc][3] = *(const uint32_t*)&Qk[(r8 + 8) * 128 + 2 * q4 + 8];
        }
    }

    float oacc[4][4];
    #pragma unroll
    for (int dn = 0; dn < 4; dn++)
        #pragma unroll
        for (int u = 0; u < 4; u++) oacc[dn][u] = 0.0f;
    float lrow0 = 0.0f, lrow1 = 0.0f;

    const __half* triW = g_trih + (size_t)h * ROWS;
    int L = lane;
    uint32_t kAddr = smaddr(Ksh + (((L >> 4) & 1) * 8 + (L & 7)) * KVS
                                + ((L >> 3) & 1) * 8);
    uint32_t vAddr = smaddr(Vsh + ((L & 7) + ((L >> 3) & 1) * 8) * KVS
                                + (L >> 4) * 8);

    #pragma unroll 1
    for (int kb = 0; kb < 12; kb++) {
        int kbase = kb * 32;
        uint32_t kbB = (uint32_t)kbase * (KVS * 2);

        float sacc[4][4];
        #pragma unroll
        for (int nt = 0; nt < 4; nt++)
            #pragma unroll
            for (int u = 0; u < 4; u++) sacc[nt][u] = 0.0f;

        #pragma unroll
        for (int dc = 0; dc < 2; dc++) {
            uint32_t b0[4], b1[4];
            ldsm4(b0, kAddr + kbB + dc * 32);
            ldsm4(b1, kAddr + kbB + 16 * KVS * 2 + dc * 32);
            mma16(sacc[0], qa[dc], b0[0], b0[1]);
            mma16(sacc[1], qa[dc], b0[2], b0[3]);
            mma16(sacc[2], qa[dc], b1[0], b1[1]);
            mma16(sacc[3], qa[dc], b1[2], b1[3]);
        }

        {
            int qrow = qbase + r8;
            const __half* t0p = triW + (size_t)qrow * J_DIM + kbase + 2 * q4;
            const __half* t1p = t0p + 8 * J_DIM;
            #pragma unroll
            for (int nt = 0; nt < 4; nt++) {
                float2 tA = __half22float2(*(const __half2*)(t0p + nt * 8));
                float2 tB = __half22float2(*(const __half2*)(t1p + nt * 8));
                float2 mv = *(const float2*)(mb + kbase + nt * 8 + 2 * q4);
                float* s = sacc[nt];
                s[0] = ex2(fminf(s[0] + tA.x + mv.x, 15.0f));
                s[1] = ex2(fminf(s[1] + tA.y + mv.y, 15.0f));
                s[2] = ex2(fminf(s[2] + tB.x + mv.x, 15.0f));
                s[3] = ex2(fminf(s[3] + tB.y + mv.y, 15.0f));
                lrow0 += s[0] + s[1];
                lrow1 += s[2] + s[3];
            }
        }

        #pragma unroll
        for (int kc = 0; kc < 2; kc++) {
            uint32_t pa[4];
            pa[0] = pack_h2(sacc[2*kc][0],   sacc[2*kc][1]);
            pa[1] = pack_h2(sacc[2*kc][2],   sacc[2*kc][3]);
            pa[2] = pack_h2(sacc[2*kc+1][0], sacc[2*kc+1][1]);
            pa[3] = pack_h2(sacc[2*kc+1][2], sacc[2*kc+1][3]);

            uint32_t vb0[4], vb1[4];
            uint32_t vOff = kbB + (uint32_t)kc * 16 * KVS * 2;
            ldsm4t(vb0, vAddr + vOff);
            ldsm4t(vb1, vAddr + vOff + 32);
            mma16(oacc[0], pa, vb0[0], vb0[1]);
            mma16(oacc[1], pa, vb0[2], vb0[3]);
            mma16(oacc[2], pa, vb1[0], vb1[1]);
            mma16(oacc[3], pa, vb1[2], vb1[3]);
        }
    }

    lrow0 += __shfl_xor_sync(~0u, lrow0, 1);
    lrow0 += __shfl_xor_sync(~0u, lrow0, 2);
    lrow1 += __shfl_xor_sync(~0u, lrow1, 1);
    lrow1 += __shfl_xor_sync(~0u, lrow1, 2);

    {
        float inv0 = 1.0f / fmaxf(lrow0, 1e-30f);
        float inv1 = 1.0f / fmaxf(lrow1, 1e-30f);
        size_t row0 = ((size_t)i * J_DIM + qbase + r8) * 128 + h * 32;
        size_t row1 = row0 + (size_t)8 * 128;
        #pragma unroll
        for (int dn = 0; dn < 4; dn++) {
            int c = dn * 8 + 2 * q4;
            float2 gv0 = __half22float2(*(const __half2*)&g_gh[row0 + c]);
            float2 gv1 = __half22float2(*(const __half2*)&g_gh[row1 + c]);
            *(uint32_t*)&g_oh[row0 + c] =
                pack_h2(oacc[dn][0] * inv0 * gv0.x, oacc[dn][1] * inv0 * gv0.y);
            *(uint32_t*)&g_oh[row1 + c] =
                pack_h2(oacc[dn][2] * inv1 * gv1.x, oacc[dn][3] * inv1 * gv1.y);
        }
    }
}

// ---------------- Kernel 3: output projection (fp16 MMA) ------------------
__global__ __launch_bounds__(256, 3) void out_kernel(
    const float* __restrict__ bo, float* __restrict__ out)
{
    extern __shared__ __half shh[];
    __half* As16 = shh;                  // [64][SAH]
    __half* Bs16 = As16 + 64 * SAH;      // [128][SBH]; reused as fp32 epilogue

    int m0 = blockIdx.x * 64;
    int tid = threadIdx.x, wid = tid >> 5, lane = tid & 31;
    int warpM = (wid >> 2) * 32, warpN = (wid & 3) * 32;
    int q4 = lane & 3, r8 = lane >> 2;

    const uint4* A4 = (const uint4*)(g_oh + (size_t)m0 * 128);
    #pragma unroll
    for (int it = 0; it < 4; it++) {
        int idx = tid + it * 256;
        int rr = idx >> 4, c8 = idx & 15;
        *(uint4*)(As16 + rr * SAH + c8 * 8) = A4[idx];
    }
    const uint4* Wh = (const uint4*)g_woh;
    #pragma unroll
    for (int it = 0; it < 8; it++) {
        int idx = tid + it * 256;
        int kk = idx >> 4, c8 = idx & 15;
        *(uint4*)&Bs16[kk * SBH + c8 * 8] = Wh[idx];
    }
    __syncthreads();

    int L = lane;
    uint32_t aAddr = smaddr(As16 + (warpM + (L & 7) + ((L >> 3) & 1) * 8) * SAH
                                 + (L >> 4) * 8);
    uint32_t bAddr = smaddr(Bs16 + ((L & 7) + ((L >> 3) & 1) * 8) * SBH
                                 + warpN + (L >> 4) * 8);

    float acc[2][4][4];
    #pragma unroll
    for (int mt = 0; mt < 2; mt++)
        #pragma unroll
        for (int nt = 0; nt < 4; nt++)
            #pragma unroll
            for (int u = 0; u < 4; u++) acc[mt][nt][u] = 0.0f;

    #pragma unroll
    for (int kc = 0; kc < 8; kc++) {
        uint32_t a0[4], a1[4], b0[4], b1[4];
        ldsm4 (a0, aAddr + kc * 32);
        ldsm4 (a1, aAddr + kc * 32 + 16 * SAH * 2);
        ldsm4t(b0, bAddr + kc * 16 * SBH * 2);
        ldsm4t(b1, bAddr + kc * 16 * SBH * 2 + 32);
        mma16(acc[0][0], a0, b0[0], b0[1]);
        mma16(acc[0][1], a0, b0[2], b0[3]);
        mma16(acc[0][2], a0, b1[0], b1[1]);
        mma16(acc[0][3], a0, b1[2], b1[3]);
        mma16(acc[1][0], a1, b0[0], b0[1]);
        mma16(acc[1][1], a1, b0[2], b0[3]);
        mma16(acc[1][2], a1, b1[0], b1[1]);
        mma16(acc[1][3], a1, b1[2], b1[3]);
    }

    // ---- fp32 epilogue via smem: conflict-free STS.64, coalesced STG.128 ----
    __syncthreads();
    float* Es32 = (float*)Bs16;          // [64][SEF] fp32 (34816 B fits exactly)
    #pragma unroll
    for (int mt = 0; mt < 2; mt++) {
        int r0 = warpM + mt * 16 + r8;
        #pragma unroll
        for (int nt = 0; nt < 4; nt++) {
            int col = warpN + nt * 8 + 2 * q4;
            float b0v = bo[col], b1v = bo[col + 1];
            *(float2*)&Es32[r0 * SEF + col] =
                make_float2(acc[mt][nt][0] + b0v, acc[mt][nt][1] + b1v);
            *(float2*)&Es32[(r0 + 8) * SEF + col] =
                make_float2(acc[mt][nt][2] + b0v, acc[mt][nt][3] + b1v);
        }
    }
    __syncthreads();
    float4* O4 = (float4*)(out + (size_t)m0 * 128);
    #pragma unroll
    for (int it = 0; it < 8; it++) {
        int idx = tid + it * 256;                // 0..2047 float4s
        int rr = idx >> 5, c4 = idx & 31;
        O4[idx] = *(float4*)&Es32[rr * SEF + c4 * 4];
    }
}

// ---------------- launch ---------------------------------------------------
extern "C" void kernel_launch(void* const* d_in, const int* in_sizes, int n_in,
                              void* d_out, int out_size)
{
    const float* x     = (const float*)d_in[0];
    const float* mask  = (const float*)d_in[1];
    const float* ln_g  = (const float*)d_in[2];
    const float* ln_b  = (const float*)d_in[3];
    const float* w_tri = (const float*)d_in[4];
    const float* wq    = (const float*)d_in[5];
    const float* wk    = (const float*)d_in[6];
    const float* wv    = (const float*)d_in[7];
    const float* wg    = (const float*)d_in[8];
    const float* bg    = (const float*)d_in[9];
    const float* wo    = (const float*)d_in[10];
    const float* bo    = (const float*)d_in[11];
    float* out = (float*)d_out;

    const int SMEM_GEMM = 64 * SAH * 2 + 128 * SBH * 2;     // 52224
    const int SMEM_ATTN = 2 * 384 * KVS * 2 + 384 * 4;      // 62976
    cudaFuncSetAttribute(proj_kernel,
                         cudaFuncAttributeMaxDynamicSharedMemorySize, SMEM_GEMM);
    cudaFuncSetAttribute(out_kernel,
                         cudaFuncAttributeMaxDynamicSharedMemorySize, SMEM_GEMM);
    cudaFuncSetAttribute(attn_kernel,
                         cudaFuncAttributeMaxDynamicSharedMemorySize, SMEM_ATTN);

    cvt_kernel<<<16, 256>>>(wq, wk, wv, wg, wo);
    proj_kernel<<<ROWS / 64, 256, SMEM_GEMM>>>(x, ln_g, ln_b, w_tri, bg);
    attn_kernel<<<dim3(I_DIM, H_DIM), 768, SMEM_ATTN>>>(mask);
    out_kernel<<<ROWS / 64, 256, SMEM_GEMM>>>(bo, out);
}